// round 15
// baseline (speedup 1.0000x reference)
#include <cuda_runtime.h>
#include <math.h>

// Problem constants
#define B_   2
#define C_   4
#define F_   512
#define H_   8
#define W_   1024
#define DH_  64
#define KW   3
#define BC_  (B_*C_)          // 8
#define BCH_ (B_*C_*H_)       // 64
#define PLANE_ (F_*W_)        // 524288
#define TOT_   (B_*C_*F_*W_)  // 4194304
#define WSZ_  (C_*F_*F_)      // 1048576 = 2^20

// k-permutation within 8-groups (contraction dims of all mma kernels):
// stored position of logical l:  pi(l) = 2*(l&3) + (l>>2)
// inverse: logical of stored s:  l(s) = (s&1)*4 + (s>>1)
// => stored order of a group = {l0,l4,l1,l5,l2,l6,l3,l7}
// mma fragment (logical t4, t4+4) sits at stored (2*t4, 2*t4+1): one LDS.64.

// ---------------------------------------------------------------------------
// Scratch (device globals; no allocations allowed)
// ---------------------------------------------------------------------------
__device__ float g_lin[3][TOT_];     // q,k,v linear outputs [bc][f][w]
__device__ float g_conv[3][TOT_];    // V conv output uses slot 2
__device__ float g_xt[TOT_];         // x transposed [bc][w][f~pi], tf32-rounded
__device__ float g_qt[TOT_];         // Q conv+rot transposed [bch][w][d~pi]
__device__ float g_kt[TOT_];         // K conv+rot transposed [bch][w][d~pi]
__device__ float g_atT[TOT_];        // attention out [bc][w][f~pi], tf32-rounded
__device__ float g_wr[4][WSZ_];      // tf32-rounded weights, f_in dim pi-permuted
__device__ float2 g_rottab[32 * 1024];

// ---------------------------------------------------------------------------
// helpers
// ---------------------------------------------------------------------------
__device__ __forceinline__ unsigned tf32r(float x) {
    unsigned u;
    asm("cvt.rna.tf32.f32 %0, %1;" : "=r"(u) : "f"(x));
    return u;
}
__device__ __forceinline__ float tf32f(float x) { return __uint_as_float(tf32r(x)); }
__device__ __forceinline__ unsigned smem_u32(const void* p) {
    unsigned a;
    asm("{ .reg .u64 t; cvta.to.shared.u64 t, %1; cvt.u32.u64 %0, t; }" : "=r"(a) : "l"(p));
    return a;
}
__device__ __forceinline__ void cp16(unsigned dst, const void* src) {
    asm volatile("cp.async.cg.shared.global [%0], [%1], 16;" :: "r"(dst), "l"(src));
}
#define CP_COMMIT() asm volatile("cp.async.commit_group;")
#define CP_WAIT0()  asm volatile("cp.async.wait_group 0;")

#define MMA8(d, a, b) \
    asm volatile("mma.sync.aligned.m16n8k8.row.col.f32.tf32.tf32.f32 " \
        "{%0,%1,%2,%3}, {%4,%5,%6,%7}, {%8,%9}, {%0,%1,%2,%3};" \
        : "+f"((d)[0]), "+f"((d)[1]), "+f"((d)[2]), "+f"((d)[3]) \
        : "r"((a)[0]), "r"((a)[1]), "r"((a)[2]), "r"((a)[3]), \
          "r"((b)[0]), "r"((b)[1]))

// ---------------------------------------------------------------------------
// Rotary cos/sin table
// ---------------------------------------------------------------------------
__global__ void __launch_bounds__(256) rot_table_kernel()
{
    int id = blockIdx.x * 256 + threadIdx.x;
    if (id >= 32 * 1024) return;
    int j = id >> 10, w = id & (W_ - 1);
    float inv = (float)exp(-log(10000.0) * ((double)(2 * j) / 64.0));
    float ang = (float)w * inv;
    float sn, cs;
    sincosf(ang, &sn, &cs);
    g_rottab[id] = make_float2(cs, sn);
}

// ---------------------------------------------------------------------------
// Round 4 weight tensors to tf32 into g_wr, f_in dim stored pi-permuted.
// ---------------------------------------------------------------------------
__global__ void __launch_bounds__(256) round_w_kernel(
    const float* __restrict__ w0, const float* __restrict__ w1,
    const float* __restrict__ w2, const float* __restrict__ w3)
{
    int i = blockIdx.x * 256 + threadIdx.x;   // over 4*WSZ_
    int which = i >> 20;
    int off   = i & (WSZ_ - 1);
    int s = off & 7;
    int src_off = (off & ~7) | ((s & 1) * 4 + (s >> 1));   // inverse-pi
    const float* src = which == 0 ? w0 : which == 1 ? w1 : which == 2 ? w2 : w3;
    (&g_wr[0][0])[i] = tf32f(src[src_off]);
}

// ---------------------------------------------------------------------------
// Plane transpose x -> xt: [bc][F][W] -> [bc][W][F~pi], tf32-rounded
// ---------------------------------------------------------------------------
__global__ void transpose_kernel(const float* __restrict__ in,
                                 float* __restrict__ out, int R)
{
    __shared__ float t[32][33];
    const int p  = blockIdx.z;
    const int r0 = blockIdx.y * 32, w0 = blockIdx.x * 32;
    const int tx = threadIdx.x, ty = threadIdx.y;        // (32, 8)
    const float* ip = in  + (size_t)p * R * W_;
    float*       op = out + (size_t)p * R * W_;
    #pragma unroll
    for (int i = 0; i < 4; i++)
        t[ty + i*8][tx] = ip[(size_t)(r0 + ty + i*8) * W_ + w0 + tx];
    __syncthreads();
    const int f  = r0 + tx;
    const int fp = (f & ~7) | (2 * (f & 3) + ((f >> 2) & 1));   // pi
    #pragma unroll
    for (int i = 0; i < 4; i++)
        op[(size_t)(w0 + ty + i*8) * R + fp] = tf32f(t[tx][ty + i*8]);
}

// ---------------------------------------------------------------------------
// tf32 GEMM (cp.async 2-stage, pi-permuted k => LDS.64 fragment loads):
//   Y[which][bc][m][n] = sum_k A_which[c][m][k] * B[bc][n][k]
// CTA 128x128, BK=32, 8 warps (2x4), warp 64x32.  smem pitch 40 floats.
// ---------------------------------------------------------------------------
#define GEMM_SMEM (2 * 2 * 128 * 40 * 4)   // 81920 B -> 2 CTAs/SM

__global__ void __launch_bounds__(256, 2) gemm_tf32_kernel(
    const float* __restrict__ A0, const float* __restrict__ A1,
    const float* __restrict__ A2,
    const float* __restrict__ Bm,   // [BC][1024][512~pi]
    float* __restrict__ Y)          // [which][BC][512][1024]
{
    extern __shared__ float gsm[];
    const int tid = threadIdx.x;
    const int wid = tid >> 5, lane = tid & 31;
    const int g = lane >> 2, t4 = lane & 3;
    const int z = blockIdx.z, which = z >> 3, bc = z & 7, c = bc & (C_ - 1);
    const int m0 = blockIdx.y * 128, n0 = blockIdx.x * 128;
    const int wm0 = (wid >> 2) * 64, wn0 = (wid & 3) * 32;

    const float* Aw = which == 0 ? A0 : which == 1 ? A1 : A2;
    const float* Ab = Aw + ((size_t)c  * F_ + m0) * F_;
    const float* Bb = Bm + ((size_t)bc * W_ + n0) * F_;
    const unsigned s0 = smem_u32(gsm);

    #define ISSUE(kt, b) do {                                                  \
        unsigned aB = s0 + (b) * 40960;                                        \
        unsigned bB = aB + 20480;                                              \
        _Pragma("unroll")                                                      \
        for (int t = 0; t < 4; t++) {                                          \
            int ch = tid + t * 256;                                            \
            int row = ch >> 3, c4 = (ch & 7) * 4;                              \
            cp16(aB + (unsigned)(row * 40 + c4) * 4,                           \
                 Ab + (size_t)row * F_ + (kt) * 32 + c4);                      \
            cp16(bB + (unsigned)(row * 40 + c4) * 4,                           \
                 Bb + (size_t)row * F_ + (kt) * 32 + c4);                      \
        }                                                                      \
        CP_COMMIT();                                                           \
    } while (0)

    float acc[4][4][4] = {};
    ISSUE(0, 0);

    for (int kt = 0; kt < 16; kt++) {
        const int buf = kt & 1;
        CP_WAIT0();
        __syncthreads();
        if (kt + 1 < 16) ISSUE(kt + 1, buf ^ 1);

        const float* As = gsm + buf * 10240;
        const float* Bs = As + 5120;
        #pragma unroll
        for (int k8 = 0; k8 < 4; k8++) {
            const int kk = k8 * 8;
            unsigned a[4][4], b[4][2];
            #pragma unroll
            for (int mf = 0; mf < 4; mf++) {
                int r = wm0 + mf*16 + g;
                float2 p = *(const float2*)&As[r*40 + kk + 2*t4];
                float2 q = *(const float2*)&As[(r+8)*40 + kk + 2*t4];
                a[mf][0] = __float_as_uint(p.x);
                a[mf][1] = __float_as_uint(q.x);
                a[mf][2] = __float_as_uint(p.y);
                a[mf][3] = __float_as_uint(q.y);
            }
            #pragma unroll
            for (int nf = 0; nf < 4; nf++) {
                int r = wn0 + nf*8 + g;
                float2 p = *(const float2*)&Bs[r*40 + kk + 2*t4];
                b[nf][0] = __float_as_uint(p.x);
                b[nf][1] = __float_as_uint(p.y);
            }
            #pragma unroll
            for (int mf = 0; mf < 4; mf++)
                #pragma unroll
                for (int nf = 0; nf < 4; nf++)
                    MMA8(acc[mf][nf], a[mf], b[nf]);
        }
    }
    #undef ISSUE

    float* Yb = Y + (size_t)which * TOT_ + (size_t)bc * PLANE_;
    #pragma unroll
    for (int mf = 0; mf < 4; mf++) {
        #pragma unroll
        for (int nf = 0; nf < 4; nf++) {
            int m = m0 + wm0 + mf*16 + g;
            int n = n0 + wn0 + nf*8 + 2*t4;
            float* y0 = Yb + (size_t)m * W_ + n;
            *(float2*)y0          = make_float2(acc[mf][nf][0], acc[mf][nf][1]);
            *(float2*)(y0 + 8*W_) = make_float2(acc[mf][nf][2], acc[mf][nf][3]);
        }
    }
}

// ---------------------------------------------------------------------------
// FUSED conv + bias + rotary + transpose for Q/K:
//   lin [bc][f][w] -> T [bch][w][d~pi]   (d stored pi-permuted within 8-groups)
// ---------------------------------------------------------------------------
__global__ void __launch_bounds__(256) convrot_t_kernel(
    const float* __restrict__ X, const float* __restrict__ Wc,
    const float* __restrict__ bias, float* __restrict__ T)
{
    __shared__ float ws[C_*C_*KW];
    __shared__ float bs[C_];
    __shared__ float t[128][65];

    const int tid = threadIdx.x;
    if (tid < C_*C_*KW) ws[tid] = Wc[tid];
    if (tid < C_)       bs[tid] = bias[tid];
    __syncthreads();

    const int w0 = blockIdx.x * 128;
    const int h  = blockIdx.y;
    const int bc = blockIdx.z;
    const int b  = bc >> 2, o = bc & (C_ - 1);

    #pragma unroll
    for (int tk = 0; tk < 16; tk++) {
        int id = tid + tk * 256;          // 0..4095
        int wl = id & 127;
        int j  = id >> 7;                 // 0..31
        int w  = w0 + wl;
        int f0 = h * DH_ + 2 * j;

        float s0 = bs[o], s1 = bs[o];
        #pragma unroll
        for (int i = 0; i < C_; i++) {
            const float* x0 = X + ((size_t)(b*C_ + i) * F_ + f0) * W_ + w;
            const float* x1 = x0 + W_;
            const float* wr = ws + (o*C_ + i) * KW;
            if (w > 0)      { s0 += wr[0] * x0[-1]; s1 += wr[0] * x1[-1]; }
                              s0 += wr[1] * x0[0];  s1 += wr[1] * x1[0];
            if (w < W_ - 1) { s0 += wr[2] * x0[1];  s1 += wr[2] * x1[1]; }
        }
        float2 cssn = g_rottab[j * W_ + w];
        t[wl][2*j]     = tf32f(s0 * cssn.x - s1 * cssn.y);
        t[wl][2*j + 1] = tf32f(s1 * cssn.x + s0 * cssn.y);
    }
    __syncthreads();

    // Phase 2: write T[bch][w][d~pi]; each thread handles one 8-group of d.
    const int bch = bc * H_ + h;
    float* Tb = T + ((size_t)bch * W_ + w0) * DH_;
    #pragma unroll
    for (int p = 0; p < 4; p++) {
        int gi = tid + p * 256;           // 0..1023 (128 w x 8 groups)
        int wl = gi >> 3;
        int ko = (gi & 7) * 8;
        const float* tr = &t[wl][ko];
        // stored order = {l0,l4,l1,l5,l2,l6,l3,l7}
        float4 v0 = make_float4(tr[0], tr[4], tr[1], tr[5]);
        float4 v1 = make_float4(tr[2], tr[6], tr[3], tr[7]);
        float* ob = Tb + (size_t)wl * DH_ + ko;
        *(float4*)ob       = v0;
        *(float4*)(ob + 4) = v1;
    }
}

// ---------------------------------------------------------------------------
// Conv2d + bias for V (tf32-rounded output, layout unchanged [bc][f][w])
// ---------------------------------------------------------------------------
__global__ void __launch_bounds__(256) conv_v_kernel(
    const float* __restrict__ X, const float* __restrict__ Wc,
    const float* __restrict__ bias, float* __restrict__ Y)
{
    __shared__ float ws[C_*C_*KW];
    __shared__ float bs[C_];
    if (threadIdx.x < C_*C_*KW) ws[threadIdx.x] = Wc[threadIdx.x];
    if (threadIdx.x < C_)       bs[threadIdx.x] = bias[threadIdx.x];
    __syncthreads();

    int idx = blockIdx.x * 256 + threadIdx.x;     // over TOT_/2
    if (idx >= TOT_/2) return;
    int w  = idx & (W_ - 1);
    int fp = (idx >> 10) & 255;
    int o  = (idx >> 18) & (C_ - 1);
    int b  = idx >> 20;
    int f0 = fp * 2;

    float s0 = bs[o], s1 = bs[o];
    #pragma unroll
    for (int i = 0; i < C_; i++) {
        const float* x0 = X + ((size_t)(b*C_ + i) * F_ + f0) * W_ + w;
        const float* x1 = x0 + W_;
        const float* wr = ws + (o*C_ + i) * KW;
        if (w > 0)       { s0 += wr[0] * x0[-1]; s1 += wr[0] * x1[-1]; }
                           s0 += wr[1] * x0[0];  s1 += wr[1] * x1[0];
        if (w < W_ - 1)  { s0 += wr[2] * x0[1];  s1 += wr[2] * x1[1]; }
    }

    size_t obase = ((size_t)(b*C_ + o) * F_ + f0) * W_ + w;
    Y[obase]      = tf32f(s0);
    Y[obase + W_] = tf32f(s1);
}

// ---------------------------------------------------------------------------
// qk = scale*Qt.Kt^T + prev + mask  (tf32 mma; Qt/Kt d-dim pi-permuted).
// Per (bch): M=N=1024, K=64.  CTA 128x128, one-shot smem (pitch 72), 8 warps.
// Fragment loads are LDS.64 (pitch 72 = 8 mod 32: conflict-free).
// ---------------------------------------------------------------------------
#define QK_SMEM (2 * 128 * 72 * 4)   // 73728 B

__global__ void __launch_bounds__(256, 2) qk_mma_kernel(
    const float* __restrict__ Qt, const float* __restrict__ Kt,
    const float* __restrict__ prev, const float* __restrict__ mask,
    float* __restrict__ qk)
{
    extern __shared__ float qsm[];
    float* Qs = qsm;             // [128][72]
    float* Ks = qsm + 128 * 72;  // [128][72]

    const int tid = threadIdx.x;
    const int wid = tid >> 5, lane = tid & 31;
    const int g = lane >> 2, t4 = lane & 3;
    const int bch = blockIdx.z;
    const int q0 = blockIdx.y * 128, k0 = blockIdx.x * 128;
    const int wm0 = (wid >> 2) * 64, wn0 = (wid & 3) * 32;

    const float* Qb = Qt + ((size_t)bch * W_ + q0) * DH_;
    const float* Kb = Kt + ((size_t)bch * W_ + k0) * DH_;

    #pragma unroll
    for (int t = 0; t < 8; t++) {
        int idx = tid + t * 256;          // 0..2047
        int row = idx >> 4;
        int c4  = (idx & 15) * 4;
        *(float4*)&Qs[row*72 + c4] = *(const float4*)(Qb + (size_t)row * DH_ + c4);
        *(float4*)&Ks[row*72 + c4] = *(const float4*)(Kb + (size_t)row * DH_ + c4);
    }
    __syncthreads();

    float acc[4][4][4] = {};
    #pragma unroll
    for (int k8 = 0; k8 < 8; k8++) {
        const int kk = k8 * 8;
        unsigned a[4][4], b[4][2];
        #pragma unroll
        for (int mf = 0; mf < 4; mf++) {
            int r = wm0 + mf*16 + g;
            float2 p = *(const float2*)&Qs[r*72 + kk + 2*t4];
            float2 q = *(const float2*)&Qs[(r+8)*72 + kk + 2*t4];
            a[mf][0] = __float_as_uint(p.x);
            a[mf][1] = __float_as_uint(q.x);
            a[mf][2] = __float_as_uint(p.y);
            a[mf][3] = __float_as_uint(q.y);
        }
        #pragma unroll
        for (int nf = 0; nf < 4; nf++) {
            int r = wn0 + nf*8 + g;
            float2 p = *(const float2*)&Ks[r*72 + kk + 2*t4];
            b[nf][0] = __float_as_uint(p.x);
            b[nf][1] = __float_as_uint(p.y);
        }
        #pragma unroll
        for (int mf = 0; mf < 4; mf++)
            #pragma unroll
            for (int nf = 0; nf < 4; nf++)
                MMA8(acc[mf][nf], a[mf], b[nf]);
    }

    const float scale = 0.044194173824159216f;   // 1/sqrt(512)
    #pragma unroll
    for (int mf = 0; mf < 4; mf++) {
        #pragma unroll
        for (int nf = 0; nf < 4; nf++) {
            int q  = q0 + wm0 + mf*16 + g;
            int kp = k0 + wn0 + nf*8 + 2*t4;
            #pragma unroll
            for (int rr = 0; rr < 2; rr++) {
                int qq = q + rr * 8;
                size_t o = ((size_t)bch * W_ + qq) * W_ + kp;
                float2 pv = *(const float2*)(prev + o);
                float2 mv = *(const float2*)(mask + (size_t)qq * W_ + kp);
                float2 r;
                r.x = acc[mf][nf][2*rr+0] * scale + pv.x + mv.x;
                r.y = acc[mf][nf][2*rr+1] * scale + pv.y + mv.y;
                *(float2*)(qk + o) = r;
            }
        }
    }
}

// ---------------------------------------------------------------------------
// AV with fused row-sum; key-dim pi-permuted INTERNALLY (both Ps and Vs),
// pitch 72 => LDS.64 fragment loads.
//   AT[bc][q][pi(h*64+d)] = (1/S_q) * sum_k exp(qk) * V
// CTA: 128 q x 64 d per bch.  BK=64, 16 K-iters.  8 warps (4x2), warp 32x32.
// Row-sum slots [128][8]: one owner per 8-group, fixed order => deterministic.
// ---------------------------------------------------------------------------
#define AV_SMEM ((128*72 + 64*72 + 128*8 + 128) * 4)   // 59904 B

__global__ void __launch_bounds__(256, 2) av_mma_kernel(
    const float* __restrict__ qk, const float* __restrict__ V,
    float* __restrict__ AT)
{
    extern __shared__ float avs[];
    float* Ps   = avs;                   // [128][72]
    float* Vs   = avs + 128 * 72;        // [64][72]
    float* ssum = avs + 128*72 + 64*72;  // [128][8]
    float* srs  = ssum + 128*8;          // [128]

    const int tid = threadIdx.x;
    const int wid = tid >> 5, lane = tid & 31;
    const int g = lane >> 2, t4 = lane & 3;
    const int bch = blockIdx.y;
    const int q0  = blockIdx.x * 128;
    const int h   = bch & (H_ - 1);
    const int bc  = bch >> 3;
    const int wm0 = (wid >> 1) * 32, wn0 = (wid & 1) * 32;

    const float* qrow = qk + ((size_t)bch * W_ + q0) * W_;
    const float* Vb   = V + ((size_t)bc * F_ + h * DH_) * W_;

    // zero row-sum slots (1024)
    #pragma unroll
    for (int t = 0; t < 4; t++) ssum[tid + t * 256] = 0.f;

    float acc[2][4][4] = {};
    for (int kt = 0; kt < 16; kt++) {
        const int k0 = kt * 64;
        __syncthreads();
        // Ps fill: 1024 8-groups (128 rows x 8), 4 per thread, stored pi-order
        #pragma unroll
        for (int t = 0; t < 4; t++) {
            int gi  = tid + t * 256;          // 0..1023
            int row = gi >> 3;
            int ko  = (gi & 7) * 8;
            const float* src = qrow + (size_t)row * W_ + k0 + ko;
            float4 xa = *(const float4*)src;
            float4 xb = *(const float4*)(src + 4);
            float e0 = __expf(xa.x), e1 = __expf(xa.y), e2 = __expf(xa.z), e3 = __expf(xa.w);
            float e4 = __expf(xb.x), e5 = __expf(xb.y), e6 = __expf(xb.z), e7 = __expf(xb.w);
            ssum[row * 8 + (gi & 7)] += ((e0 + e1) + (e2 + e3)) + ((e4 + e5) + (e6 + e7));
            float* dst = &Ps[row*72 + ko];
            // stored order = {e0,e4,e1,e5,e2,e6,e3,e7}
            *(uint4*)dst       = make_uint4(tf32r(e0), tf32r(e4), tf32r(e1), tf32r(e5));
            *(uint4*)(dst + 4) = make_uint4(tf32r(e2), tf32r(e6), tf32r(e3), tf32r(e7));
        }
        // Vs fill: 512 8-groups (64 rows x 8), 2 per thread, same pi-order
        #pragma unroll
        for (int t = 0; t < 2; t++) {
            int gi  = tid + t * 256;          // 0..511
            int row = gi >> 3;
            int ko  = (gi & 7) * 8;
            const float* src = Vb + (size_t)row * W_ + k0 + ko;
            float4 xa = *(const float4*)src;
            float4 xb = *(const float4*)(src + 4);
            float* dst = &Vs[row*72 + ko];
            *(float4*)dst       = make_float4(xa.x, xb.x, xa.y, xb.y);
            *(float4*)(dst + 4) = make_float4(xa.z, xb.z, xa.w, xb.w);
        }
        __syncthreads();
        #pragma unroll
        for (int k8 = 0; k8 < 8; k8++) {
            const int kk = k8 * 8;
            unsigned a[2][4], b[4][2];
            #pragma unroll
            for (int mf = 0; mf < 2; mf++) {
                int r = wm0 + mf*16 + g;
                float2 p = *(const float2*)&Ps[r*72 + kk + 2*t4];
                float2 q = *(const float2*)&Ps[(r+8)*72 + kk + 2*t4];
                a[mf][0] = __float_as_uint(p.x);
                a[mf][1] = __float_as_uint(q.x);
                a[mf][2] = __float_as_uint(p.y);
                a[mf][3] = __float_as_uint(q.y);
            }
            #pragma unroll
            for (int nf = 0; nf < 4; nf++) {
                int r = wn0 + nf*8 + g;
                float2 p = *(const float2*)&Vs[r*72 + kk + 2*t4];
                b[nf][0] = __float_as_uint(p.x);
                b[nf][1] = __float_as_uint(p.y);
            }
            #pragma unroll
            for (int mf = 0; mf < 2; mf++)
                #pragma unroll
                for (int nf = 0; nf < 4; nf++)
                    MMA8(acc[mf][nf], a[mf], b[nf]);
        }
    }

    // final row-sum reduction (fixed order => deterministic)
    __syncthreads();
    if (tid < 128) {
        float s = 0.f;
        #pragma unroll
        for (int j = 0; j < 8; j++) s += ssum[tid * 8 + j];
        srs[tid] = 1.0f / s;
    }
    __syncthreads();

    // pi positions for the output pair (2*t4, 2*t4+1) within the d 8-group
    const int l0 = 2 * t4,     s0p = 2 * (l0 & 3) + (l0 >> 2);
    const int l1 = 2 * t4 + 1, s1p = 2 * (l1 & 3) + (l1 >> 2);

    #pragma unroll
    for (int mf = 0; mf < 2; mf++) {
        #pragma unroll
        for (int nf = 0; nf < 4; nf++) {
            int ql = wm0 + mf*16 + g;
            int dg = wn0 + nf*8;                 // 8-group base of d
            #pragma unroll
            for (int rr = 0; rr < 2; rr++) {
                int q = ql + rr * 8;
                float sc = srs[q];
                size_t ob = ((size_t)bc * W_ + q0 + q) * F_ + h * DH_ + dg;
                AT[ob + s0p] = tf32f(acc[mf][nf][2*rr+0] * sc);
                AT[ob + s1p] = tf32f(acc[mf][nf][2*rr+1] * sc);
            }
        }
    }
}

// ---------------------------------------------------------------------------
extern "C" void kernel_launch(void* const* d_in, const int* in_sizes, int n_in,
                              void* d_out, int out_size)
{
    const float* x    = (const float*)d_in[0];
    const float* prev = (const float*)d_in[1];
    const float* mask = (const float*)d_in[2];
    const float* wq   = (const float*)d_in[3];
    const float* wqc  = (const float*)d_in[4];
    const float* bq   = (const float*)d_in[5];
    const float* wk   = (const float*)d_in[6];
    const float* wkc  = (const float*)d_in[7];
    const float* bk   = (const float*)d_in[8];
    const float* wv   = (const float*)d_in[9];
    const float* wvc  = (const float*)d_in[10];
    const float* bv   = (const float*)d_in[11];
    const float* wo   = (const float*)d_in[12];

    float* out = (float*)d_out;            // [B,C,F,W]
    float* qk  = out + (size_t)TOT_;       // [B,C,H,W,W]

    float *lin_base, *conv_base, *xt, *qt, *kt, *atT, *wr;
    cudaGetSymbolAddress((void**)&lin_base,  g_lin);
    cudaGetSymbolAddress((void**)&conv_base, g_conv);
    cudaGetSymbolAddress((void**)&xt,  g_xt);
    cudaGetSymbolAddress((void**)&qt,  g_qt);
    cudaGetSymbolAddress((void**)&kt,  g_kt);
    cudaGetSymbolAddress((void**)&atT, g_atT);
    cudaGetSymbolAddress((void**)&wr,  g_wr);

    float* lin0  = lin_base;
    float* cbuf2 = conv_base + (size_t)2*TOT_;

    rot_table_kernel<<<128, 256>>>();
    round_w_kernel<<<(4*WSZ_)/256, 256>>>(wq, wk, wv, wo);

    // x [bc][f][w] -> xt [bc][w][f~pi] (rounded)
    transpose_kernel<<<dim3(32, 16, BC_), dim3(32, 8)>>>(x, xt, F_);

    cudaFuncSetAttribute(gemm_tf32_kernel,
                         cudaFuncAttributeMaxDynamicSharedMemorySize, GEMM_SMEM);
    // combined QKV: grid.z = 3*8
    gemm_tf32_kernel<<<dim3(W_/128, F_/128, 24), 256, GEMM_SMEM>>>(
        wr + 0*WSZ_, wr + 1*WSZ_, wr + 2*WSZ_, xt, lin0);

    // fused conv+rotary+transpose for Q,K -> qt/kt [bch][w][d~pi]
    dim3 cg(W_/128, H_, BC_);   // 8, 8, 8
    convrot_t_kernel<<<cg, 256>>>(lin0 + 0*(size_t)TOT_, wqc, bq, qt);
    convrot_t_kernel<<<cg, 256>>>(lin0 + 1*(size_t)TOT_, wkc, bk, kt);
    // V conv (layout unchanged)
    conv_v_kernel<<<(TOT_/2)/256, 256>>>(lin0 + 2*(size_t)TOT_, wvc, bv, cbuf2);

    cudaFuncSetAttribute(qk_mma_kernel,
                         cudaFuncAttributeMaxDynamicSharedMemorySize, QK_SMEM);
    qk_mma_kernel<<<dim3(8, 8, BCH_), 256, QK_SMEM>>>(qt, kt, prev, mask, qk);

    cudaFuncSetAttribute(av_mma_kernel,
                         cudaFuncAttributeMaxDynamicSharedMemorySize, AV_SMEM);
    av_mma_kernel<<<dim3(W_/128, BCH_), 256, AV_SMEM>>>(qk, cbuf2, atT);

    // O gemm: which = 0 only
    gemm_tf32_kernel<<<dim3(W_/128, F_/128, 8), 256, GEMM_SMEM>>>(
        wr + 3*WSZ_, wr + 3*WSZ_, wr + 3*WSZ_, atT, out);
}

// round 16
// speedup vs baseline: 1.0240x; 1.0240x over previous
#include <cuda_runtime.h>
#include <math.h>

// Problem constants
#define B_   2
#define C_   4
#define F_   512
#define H_   8
#define W_   1024
#define DH_  64
#define KW   3
#define BC_  (B_*C_)          // 8
#define BCH_ (B_*C_*H_)       // 64
#define PLANE_ (F_*W_)        // 524288
#define TOT_   (B_*C_*F_*W_)  // 4194304
#define WSZ_  (C_*F_*F_)      // 1048576 = 2^20

// k-permutation within 8-groups (linear-GEMM k dims only):
// stored position of logical l:  pi(l) = 2*(l&3) + (l>>2)

// ---------------------------------------------------------------------------
// Scratch (device globals; no allocations allowed)
// ---------------------------------------------------------------------------
__device__ float g_lin[3][TOT_];     // q,k,v linear outputs [bc][f][w]
__device__ float g_conv[3][TOT_];    // V conv output uses slot 2
__device__ float g_xt[TOT_];         // x transposed [bc][w][f~pi], tf32-rounded
__device__ float g_qt[TOT_];         // Q conv+rot transposed [bch][w][d]
__device__ float g_kt[TOT_];         // K conv+rot transposed [bch][w][d]
__device__ float g_atT[TOT_];        // attention out [bc][w][f~pi], tf32-rounded
__device__ float g_wr[4][WSZ_];      // tf32-rounded weights, f_in dim pi-permuted
__device__ float2 g_rottab[32 * 1024];

// ---------------------------------------------------------------------------
// helpers
// ---------------------------------------------------------------------------
__device__ __forceinline__ unsigned tf32r(float x) {
    unsigned u;
    asm("cvt.rna.tf32.f32 %0, %1;" : "=r"(u) : "f"(x));
    return u;
}
__device__ __forceinline__ float tf32f(float x) { return __uint_as_float(tf32r(x)); }
__device__ __forceinline__ unsigned smem_u32(const void* p) {
    unsigned a;
    asm("{ .reg .u64 t; cvta.to.shared.u64 t, %1; cvt.u32.u64 %0, t; }" : "=r"(a) : "l"(p));
    return a;
}
__device__ __forceinline__ void cp16(unsigned dst, const void* src) {
    asm volatile("cp.async.cg.shared.global [%0], [%1], 16;" :: "r"(dst), "l"(src));
}
#define CP_COMMIT() asm volatile("cp.async.commit_group;")
#define CP_WAIT0()  asm volatile("cp.async.wait_group 0;")

#define MMA8(d, a, b) \
    asm volatile("mma.sync.aligned.m16n8k8.row.col.f32.tf32.tf32.f32 " \
        "{%0,%1,%2,%3}, {%4,%5,%6,%7}, {%8,%9}, {%0,%1,%2,%3};" \
        : "+f"((d)[0]), "+f"((d)[1]), "+f"((d)[2]), "+f"((d)[3]) \
        : "r"((a)[0]), "r"((a)[1]), "r"((a)[2]), "r"((a)[3]), \
          "r"((b)[0]), "r"((b)[1]))

// ---------------------------------------------------------------------------
// Rotary cos/sin table
// ---------------------------------------------------------------------------
__global__ void __launch_bounds__(256) rot_table_kernel()
{
    int id = blockIdx.x * 256 + threadIdx.x;
    if (id >= 32 * 1024) return;
    int j = id >> 10, w = id & (W_ - 1);
    float inv = (float)exp(-log(10000.0) * ((double)(2 * j) / 64.0));
    float ang = (float)w * inv;
    float sn, cs;
    sincosf(ang, &sn, &cs);
    g_rottab[id] = make_float2(cs, sn);
}

// ---------------------------------------------------------------------------
// Round 4 weight tensors to tf32 into g_wr, f_in dim stored pi-permuted.
// ---------------------------------------------------------------------------
__global__ void __launch_bounds__(256) round_w_kernel(
    const float* __restrict__ w0, const float* __restrict__ w1,
    const float* __restrict__ w2, const float* __restrict__ w3)
{
    int i = blockIdx.x * 256 + threadIdx.x;   // over 4*WSZ_
    int which = i >> 20;
    int off   = i & (WSZ_ - 1);
    int s = off & 7;
    int src_off = (off & ~7) | ((s & 1) * 4 + (s >> 1));   // inverse-pi
    const float* src = which == 0 ? w0 : which == 1 ? w1 : which == 2 ? w2 : w3;
    (&g_wr[0][0])[i] = tf32f(src[src_off]);
}

// ---------------------------------------------------------------------------
// Plane transpose x -> xt: [bc][F][W] -> [bc][W][F~pi], tf32-rounded
// ---------------------------------------------------------------------------
__global__ void transpose_kernel(const float* __restrict__ in,
                                 float* __restrict__ out, int R)
{
    __shared__ float t[32][33];
    const int p  = blockIdx.z;
    const int r0 = blockIdx.y * 32, w0 = blockIdx.x * 32;
    const int tx = threadIdx.x, ty = threadIdx.y;        // (32, 8)
    const float* ip = in  + (size_t)p * R * W_;
    float*       op = out + (size_t)p * R * W_;
    #pragma unroll
    for (int i = 0; i < 4; i++)
        t[ty + i*8][tx] = ip[(size_t)(r0 + ty + i*8) * W_ + w0 + tx];
    __syncthreads();
    const int f  = r0 + tx;
    const int fp = (f & ~7) | (2 * (f & 3) + ((f >> 2) & 1));   // pi
    #pragma unroll
    for (int i = 0; i < 4; i++)
        op[(size_t)(w0 + ty + i*8) * R + fp] = tf32f(t[tx][ty + i*8]);
}

// ---------------------------------------------------------------------------
// tf32 GEMM (cp.async 2-stage, pi-permuted k => LDS.64 fragment loads,
// fragment base pointers hoisted => inner-loop addresses are immediates):
//   Y[which][bc][m][n] = sum_k A_which[c][m][k] * B[bc][n][k]
// CTA 128x128, BK=32, 8 warps (2x4), warp 64x32.  smem pitch 40 floats.
// ---------------------------------------------------------------------------
#define GEMM_SMEM (2 * 2 * 128 * 40 * 4)   // 81920 B -> 2 CTAs/SM

__global__ void __launch_bounds__(256, 2) gemm_tf32_kernel(
    const float* __restrict__ A0, const float* __restrict__ A1,
    const float* __restrict__ A2,
    const float* __restrict__ Bm,   // [BC][1024][512~pi]
    float* __restrict__ Y)          // [which][BC][512][1024]
{
    extern __shared__ float gsm[];
    const int tid = threadIdx.x;
    const int wid = tid >> 5, lane = tid & 31;
    const int g = lane >> 2, t4 = lane & 3;
    const int z = blockIdx.z, which = z >> 3, bc = z & 7, c = bc & (C_ - 1);
    const int m0 = blockIdx.y * 128, n0 = blockIdx.x * 128;
    const int wm0 = (wid >> 2) * 64, wn0 = (wid & 3) * 32;

    const float* Aw = which == 0 ? A0 : which == 1 ? A1 : A2;
    const float* Ab = Aw + ((size_t)c  * F_ + m0) * F_;
    const float* Bb = Bm + ((size_t)bc * W_ + n0) * F_;
    const unsigned s0 = smem_u32(gsm);

    // hoisted per-thread fragment offsets (in floats)
    const int aoff = (wm0 + g) * 40 + 2 * t4;
    const int boff = 5120 + (wn0 + g) * 40 + 2 * t4;

    #define ISSUE(kt, b) do {                                                  \
        unsigned aB = s0 + (b) * 40960;                                        \
        unsigned bB = aB + 20480;                                              \
        _Pragma("unroll")                                                      \
        for (int t = 0; t < 4; t++) {                                          \
            int ch = tid + t * 256;                                            \
            int row = ch >> 3, c4 = (ch & 7) * 4;                              \
            cp16(aB + (unsigned)(row * 40 + c4) * 4,                           \
                 Ab + (size_t)row * F_ + (kt) * 32 + c4);                      \
            cp16(bB + (unsigned)(row * 40 + c4) * 4,                           \
                 Bb + (size_t)row * F_ + (kt) * 32 + c4);                      \
        }                                                                      \
        CP_COMMIT();                                                           \
    } while (0)

    float acc[4][4][4] = {};
    ISSUE(0, 0);

    for (int kt = 0; kt < 16; kt++) {
        const int buf = kt & 1;
        CP_WAIT0();
        __syncthreads();
        if (kt + 1 < 16) ISSUE(kt + 1, buf ^ 1);

        const float* aw = gsm + buf * 10240 + aoff;
        const float* bw = gsm + buf * 10240 + boff;
        #pragma unroll
        for (int k8 = 0; k8 < 4; k8++) {
            const int kk = k8 * 8;
            unsigned a[4][4], b[4][2];
            #pragma unroll
            for (int mf = 0; mf < 4; mf++) {
                float2 p = *(const float2*)(aw + mf*640 + kk);         // rows wm0+mf*16+g
                float2 q = *(const float2*)(aw + mf*640 + 320 + kk);   // +8 rows
                a[mf][0] = __float_as_uint(p.x);
                a[mf][1] = __float_as_uint(q.x);
                a[mf][2] = __float_as_uint(p.y);
                a[mf][3] = __float_as_uint(q.y);
            }
            #pragma unroll
            for (int nf = 0; nf < 4; nf++) {
                float2 p = *(const float2*)(bw + nf*320 + kk);
                b[nf][0] = __float_as_uint(p.x);
                b[nf][1] = __float_as_uint(p.y);
            }
            #pragma unroll
            for (int mf = 0; mf < 4; mf++)
                #pragma unroll
                for (int nf = 0; nf < 4; nf++)
                    MMA8(acc[mf][nf], a[mf], b[nf]);
        }
    }
    #undef ISSUE

    float* Yb = Y + (size_t)which * TOT_ + (size_t)bc * PLANE_;
    #pragma unroll
    for (int mf = 0; mf < 4; mf++) {
        #pragma unroll
        for (int nf = 0; nf < 4; nf++) {
            int m = m0 + wm0 + mf*16 + g;
            int n = n0 + wn0 + nf*8 + 2*t4;
            float* y0 = Yb + (size_t)m * W_ + n;
            *(float2*)y0          = make_float2(acc[mf][nf][0], acc[mf][nf][1]);
            *(float2*)(y0 + 8*W_) = make_float2(acc[mf][nf][2], acc[mf][nf][3]);
        }
    }
}

// ---------------------------------------------------------------------------
// FUSED conv + bias + rotary + transpose for Q/K:  lin [bc][f][w] -> T [bch][w][d]
// (d dim NOT permuted — feeds qk_mma's scalar-fragment path)
// ---------------------------------------------------------------------------
__global__ void __launch_bounds__(256) convrot_t_kernel(
    const float* __restrict__ X, const float* __restrict__ Wc,
    const float* __restrict__ bias, float* __restrict__ T)
{
    __shared__ float ws[C_*C_*KW];
    __shared__ float bs[C_];
    __shared__ float t[128][65];

    const int tid = threadIdx.x;
    if (tid < C_*C_*KW) ws[tid] = Wc[tid];
    if (tid < C_)       bs[tid] = bias[tid];
    __syncthreads();

    const int w0 = blockIdx.x * 128;
    const int h  = blockIdx.y;
    const int bc = blockIdx.z;
    const int b  = bc >> 2, o = bc & (C_ - 1);

    #pragma unroll
    for (int tk = 0; tk < 16; tk++) {
        int id = tid + tk * 256;          // 0..4095
        int wl = id & 127;
        int j  = id >> 7;                 // 0..31
        int w  = w0 + wl;
        int f0 = h * DH_ + 2 * j;

        float s0 = bs[o], s1 = bs[o];
        #pragma unroll
        for (int i = 0; i < C_; i++) {
            const float* x0 = X + ((size_t)(b*C_ + i) * F_ + f0) * W_ + w;
            const float* x1 = x0 + W_;
            const float* wr = ws + (o*C_ + i) * KW;
            if (w > 0)      { s0 += wr[0] * x0[-1]; s1 += wr[0] * x1[-1]; }
                              s0 += wr[1] * x0[0];  s1 += wr[1] * x1[0];
            if (w < W_ - 1) { s0 += wr[2] * x0[1];  s1 += wr[2] * x1[1]; }
        }
        float2 cssn = g_rottab[j * W_ + w];
        t[wl][2*j]     = tf32f(s0 * cssn.x - s1 * cssn.y);
        t[wl][2*j + 1] = tf32f(s1 * cssn.x + s0 * cssn.y);
    }
    __syncthreads();

    const int bch = bc * H_ + h;
    float* Tb = T + ((size_t)bch * W_ + w0) * DH_;
    const int row = tid >> 4;           // 0..15
    const int d4  = (tid & 15) * 4;
    #pragma unroll
    for (int p = 0; p < 8; p++) {
        int wl = row + p * 16;
        float4 v = make_float4(t[wl][d4], t[wl][d4+1], t[wl][d4+2], t[wl][d4+3]);
        *(float4*)(Tb + (size_t)wl * DH_ + d4) = v;
    }
}

// ---------------------------------------------------------------------------
// Conv2d + bias for V (tf32-rounded output, layout unchanged [bc][f][w])
// ---------------------------------------------------------------------------
__global__ void __launch_bounds__(256) conv_v_kernel(
    const float* __restrict__ X, const float* __restrict__ Wc,
    const float* __restrict__ bias, float* __restrict__ Y)
{
    __shared__ float ws[C_*C_*KW];
    __shared__ float bs[C_];
    if (threadIdx.x < C_*C_*KW) ws[threadIdx.x] = Wc[threadIdx.x];
    if (threadIdx.x < C_)       bs[threadIdx.x] = bias[threadIdx.x];
    __syncthreads();

    int idx = blockIdx.x * 256 + threadIdx.x;     // over TOT_/2
    if (idx >= TOT_/2) return;
    int w  = idx & (W_ - 1);
    int fp = (idx >> 10) & 255;
    int o  = (idx >> 18) & (C_ - 1);
    int b  = idx >> 20;
    int f0 = fp * 2;

    float s0 = bs[o], s1 = bs[o];
    #pragma unroll
    for (int i = 0; i < C_; i++) {
        const float* x0 = X + ((size_t)(b*C_ + i) * F_ + f0) * W_ + w;
        const float* x1 = x0 + W_;
        const float* wr = ws + (o*C_ + i) * KW;
        if (w > 0)       { s0 += wr[0] * x0[-1]; s1 += wr[0] * x1[-1]; }
                           s0 += wr[1] * x0[0];  s1 += wr[1] * x1[0];
        if (w < W_ - 1)  { s0 += wr[2] * x0[1];  s1 += wr[2] * x1[1]; }
    }

    size_t obase = ((size_t)(b*C_ + o) * F_ + f0) * W_ + w;
    Y[obase]      = tf32f(s0);
    Y[obase + W_] = tf32f(s1);
}

// ---------------------------------------------------------------------------
// qk = scale*Qt.Kt^T + prev + mask  (tf32 mma, pre-rounded Qt/Kt).
// Per (bch): M=N=1024, K=64.  CTA 128x128, one-shot smem, 8 warps (2x4).
// (R14-proven version — qk is HBM-bound; fragment path left alone)
// ---------------------------------------------------------------------------
#define QK_SMEM (2 * 128 * 68 * 4)

__global__ void __launch_bounds__(256, 2) qk_mma_kernel(
    const float* __restrict__ Qt, const float* __restrict__ Kt,
    const float* __restrict__ prev, const float* __restrict__ mask,
    float* __restrict__ qk)
{
    extern __shared__ unsigned qsm[];
    unsigned (*Qs)[68] = (unsigned (*)[68])qsm;
    unsigned (*Ks)[68] = (unsigned (*)[68])(qsm + 128 * 68);

    const int tid = threadIdx.x;
    const int wid = tid >> 5, lane = tid & 31;
    const int g = lane >> 2, t4 = lane & 3;
    const int bch = blockIdx.z;
    const int q0 = blockIdx.y * 128, k0 = blockIdx.x * 128;
    const int wm0 = (wid >> 2) * 64, wn0 = (wid & 3) * 32;

    const float* Qb = Qt + ((size_t)bch * W_ + q0) * DH_;
    const float* Kb = Kt + ((size_t)bch * W_ + k0) * DH_;

    #pragma unroll
    for (int t = 0; t < 8; t++) {
        int idx = tid + t * 256;          // 0..2047
        int row = idx >> 4;
        int c4  = (idx & 15) * 4;
        *(uint4*)&Qs[row][c4] = *(const uint4*)(Qb + (size_t)row * DH_ + c4);
        *(uint4*)&Ks[row][c4] = *(const uint4*)(Kb + (size_t)row * DH_ + c4);
    }
    __syncthreads();

    float acc[4][4][4] = {};
    #pragma unroll
    for (int k8 = 0; k8 < 8; k8++) {
        const int kk = k8 * 8;
        unsigned a[4][4], b[4][2];
        #pragma unroll
        for (int mf = 0; mf < 4; mf++) {
            int r = wm0 + mf*16 + g;
            a[mf][0] = Qs[r][kk + t4];
            a[mf][1] = Qs[r + 8][kk + t4];
            a[mf][2] = Qs[r][kk + t4 + 4];
            a[mf][3] = Qs[r + 8][kk + t4 + 4];
        }
        #pragma unroll
        for (int nf = 0; nf < 4; nf++) {
            int r = wn0 + nf*8 + g;
            b[nf][0] = Ks[r][kk + t4];
            b[nf][1] = Ks[r][kk + t4 + 4];
        }
        #pragma unroll
        for (int mf = 0; mf < 4; mf++)
            #pragma unroll
            for (int nf = 0; nf < 4; nf++)
                MMA8(acc[mf][nf], a[mf], b[nf]);
    }

    const float scale = 0.044194173824159216f;   // 1/sqrt(512)
    #pragma unroll
    for (int mf = 0; mf < 4; mf++) {
        #pragma unroll
        for (int nf = 0; nf < 4; nf++) {
            int q  = q0 + wm0 + mf*16 + g;
            int kp = k0 + wn0 + nf*8 + 2*t4;
            #pragma unroll
            for (int rr = 0; rr < 2; rr++) {
                int qq = q + rr * 8;
                size_t o = ((size_t)bch * W_ + qq) * W_ + kp;
                float2 pv = *(const float2*)(prev + o);
                float2 mv = *(const float2*)(mask + (size_t)qq * W_ + kp);
                float2 r;
                r.x = acc[mf][nf][2*rr+0] * scale + pv.x + mv.x;
                r.y = acc[mf][nf][2*rr+1] * scale + pv.y + mv.y;
                *(float2*)(qk + o) = r;
            }
        }
    }
}

// ---------------------------------------------------------------------------
// AV with fused row-sum (smem-slot accumulation, deterministic):
//   AT[bc][q][pi(h*64+d)] = (1/S_q) * sum_k exp(qk) * V
// CTA: 128 q x 64 d per bch.  BK=64, 16 K-iters.  8 warps (4x2), warp 32x32.
// (R14-proven version)
// ---------------------------------------------------------------------------
#define AV_SMEM ((128*68 + 64*68 + 128*16 + 128) * 4)

__global__ void __launch_bounds__(256, 2) av_mma_kernel(
    const float* __restrict__ qk, const float* __restrict__ V,
    float* __restrict__ AT)
{
    extern __shared__ unsigned asm_[];
    unsigned (*Ps)[68] = (unsigned (*)[68])asm_;
    unsigned (*Vs)[68] = (unsigned (*)[68])(asm_ + 128 * 68);
    float* ssum = (float*)(asm_ + 128*68 + 64*68);   // [128][16]
    float* srs  = ssum + 128*16;                     // [128]

    const int tid = threadIdx.x;
    const int wid = tid >> 5, lane = tid & 31;
    const int g = lane >> 2, t4 = lane & 3;
    const int bch = blockIdx.y;
    const int q0  = blockIdx.x * 128;
    const int h   = bch & (H_ - 1);
    const int bc  = bch >> 3;
    const int wm0 = (wid >> 1) * 32, wn0 = (wid & 1) * 32;

    const float* qrow = qk + ((size_t)bch * W_ + q0) * W_;
    const float* Vb   = V + ((size_t)bc * F_ + h * DH_) * W_;

    // zero row-sum slots
    #pragma unroll
    for (int t = 0; t < 8; t++) ssum[tid + t * 256] = 0.f;

    float acc[2][4][4] = {};
    for (int kt = 0; kt < 16; kt++) {
        const int k0 = kt * 64;
        __syncthreads();
        #pragma unroll
        for (int t = 0; t < 8; t++) {
            int idx = tid + t * 256;          // 0..2047
            int row = idx >> 4;
            int c16 = idx & 15;
            int c4  = c16 * 4;
            float4 x = *(const float4*)(qrow + (size_t)row * W_ + k0 + c4);
            float e0 = __expf(x.x), e1 = __expf(x.y);
            float e2 = __expf(x.z), e3 = __expf(x.w);
            ssum[row * 16 + c16] += (e0 + e1) + (e2 + e3);
            *(uint4*)&Ps[row][c4] = make_uint4(tf32r(e0), tf32r(e1), tf32r(e2), tf32r(e3));
        }
        #pragma unroll
        for (int t = 0; t < 4; t++) {
            int idx = tid + t * 256;          // 0..1023
            int row = idx >> 4;
            int c4  = (idx & 15) * 4;
            *(uint4*)&Vs[row][c4] = *(const uint4*)(Vb + (size_t)row * W_ + k0 + c4);
        }
        __syncthreads();
        #pragma unroll
        for (int k8 = 0; k8 < 8; k8++) {
            const int kk = k8 * 8;
            unsigned a[2][4], b[4][2];
            #pragma unroll
            for (int mf = 0; mf < 2; mf++) {
                int r = wm0 + mf*16 + g;
                a[mf][0] = Ps[r][kk + t4];
                a[mf][1] = Ps[r + 8][kk + t4];
                a[mf][2] = Ps[r][kk + t4 + 4];
                a[mf][3] = Ps[r + 8][kk + t4 + 4];
            }
            #pragma unroll
            for (int nf = 0; nf < 4; nf++) {
                int r = wn0 + nf*8 + g;
                b[nf][0] = Vs[r][kk + t4];
                b[nf][1] = Vs[r][kk + t4 + 4];
            }
            #pragma unroll
            for (int mf = 0; mf < 2; mf++)
                #pragma unroll
                for (int nf = 0; nf < 4; nf++)
                    MMA8(acc[mf][nf], a[mf], b[nf]);
        }
    }

    // final row-sum reduction (fixed order => deterministic)
    __syncthreads();
    if (tid < 128) {
        float s = 0.f;
        #pragma unroll
        for (int j = 0; j < 16; j++) s += ssum[tid * 16 + j];
        srs[tid] = 1.0f / s;
    }
    __syncthreads();

    // pi positions for the pair (2*t4, 2*t4+1) within the 8-group
    const int l0 = 2 * t4,     s0p = 2 * (l0 & 3) + (l0 >> 2);
    const int l1 = 2 * t4 + 1, s1p = 2 * (l1 & 3) + (l1 >> 2);

    #pragma unroll
    for (int mf = 0; mf < 2; mf++) {
        #pragma unroll
        for (int nf = 0; nf < 4; nf++) {
            int ql = wm0 + mf*16 + g;
            int dg = wn0 + nf*8;                 // 8-group base of d
            #pragma unroll
            for (int rr = 0; rr < 2; rr++) {
                int q = ql + rr * 8;
                float sc = srs[q];
                size_t ob = ((size_t)bc * W_ + q0 + q) * F_ + h * DH_ + dg;
                AT[ob + s0p] = tf32f(acc[mf][nf][2*rr+0] * sc);
                AT[ob + s1p] = tf32f(acc[mf][nf][2*rr+1] * sc);
            }
        }
    }
}

// ---------------------------------------------------------------------------
extern "C" void kernel_launch(void* const* d_in, const int* in_sizes, int n_in,
                              void* d_out, int out_size)
{
    const float* x    = (const float*)d_in[0];
    const float* prev = (const float*)d_in[1];
    const float* mask = (const float*)d_in[2];
    const float* wq   = (const float*)d_in[3];
    const float* wqc  = (const float*)d_in[4];
    const float* bq   = (const float*)d_in[5];
    const float* wk   = (const float*)d_in[6];
    const float* wkc  = (const float*)d_in[7];
    const float* bk   = (const float*)d_in[8];
    const float* wv   = (const float*)d_in[9];
    const float* wvc  = (const float*)d_in[10];
    const float* bv   = (const float*)d_in[11];
    const float* wo   = (const float*)d_in[12];

    float* out = (float*)d_out;            // [B,C,F,W]
    float* qk  = out + (size_t)TOT_;       // [B,C,H,W,W]

    float *lin_base, *conv_base, *xt, *qt, *kt, *atT, *wr;
    cudaGetSymbolAddress((void**)&lin_base,  g_lin);
    cudaGetSymbolAddress((void**)&conv_base, g_conv);
    cudaGetSymbolAddress((void**)&xt,  g_xt);
    cudaGetSymbolAddress((void**)&qt,  g_qt);
    cudaGetSymbolAddress((void**)&kt,  g_kt);
    cudaGetSymbolAddress((void**)&atT, g_atT);
    cudaGetSymbolAddress((void**)&wr,  g_wr);

    float* lin0  = lin_base;
    float* cbuf2 = conv_base + (size_t)2*TOT_;

    rot_table_kernel<<<128, 256>>>();
    round_w_kernel<<<(4*WSZ_)/256, 256>>>(wq, wk, wv, wo);

    // x [bc][f][w] -> xt [bc][w][f~pi] (rounded)
    transpose_kernel<<<dim3(32, 16, BC_), dim3(32, 8)>>>(x, xt, F_);

    cudaFuncSetAttribute(gemm_tf32_kernel,
                         cudaFuncAttributeMaxDynamicSharedMemorySize, GEMM_SMEM);
    // combined QKV: grid.z = 3*8
    gemm_tf32_kernel<<<dim3(W_/128, F_/128, 24), 256, GEMM_SMEM>>>(
        wr + 0*WSZ_, wr + 1*WSZ_, wr + 2*WSZ_, xt, lin0);

    // fused conv+rotary+transpose for Q,K -> qt/kt [bch][w][d]
    dim3 cg(W_/128, H_, BC_);   // 8, 8, 8
    convrot_t_kernel<<<cg, 256>>>(lin0 + 0*(size_t)TOT_, wqc, bq, qt);
    convrot_t_kernel<<<cg, 256>>>(lin0 + 1*(size_t)TOT_, wkc, bk, kt);
    // V conv (layout unchanged)
    conv_v_kernel<<<(TOT_/2)/256, 256>>>(lin0 + 2*(size_t)TOT_, wvc, bv, cbuf2);

    cudaFuncSetAttribute(qk_mma_kernel,
                         cudaFuncAttributeMaxDynamicSharedMemorySize, QK_SMEM);
    qk_mma_kernel<<<dim3(8, 8, BCH_), 256, QK_SMEM>>>(qt, kt, prev, mask, qk);

    cudaFuncSetAttribute(av_mma_kernel,
                         cudaFuncAttributeMaxDynamicSharedMemorySize, AV_SMEM);
    av_mma_kernel<<<dim3(W_/128, BCH_), 256, AV_SMEM>>>(qk, cbuf2, atT);

    // O gemm: which = 0 only
    gemm_tf32_kernel<<<dim3(W_/128, F_/128, 8), 256, GEMM_SMEM>>>(
        wr + 3*WSZ_, wr + 3*WSZ_, wr + 3*WSZ_, atT, out);
}

// round 17
// speedup vs baseline: 1.0492x; 1.0246x over previous
#include <cuda_runtime.h>
#include <math.h>

// Problem constants
#define B_   2
#define C_   4
#define F_   512
#define H_   8
#define W_   1024
#define DH_  64
#define KW   3
#define BC_  (B_*C_)          // 8
#define BCH_ (B_*C_*H_)       // 64
#define PLANE_ (F_*W_)        // 524288
#define TOT_   (B_*C_*F_*W_)  // 4194304
#define WSZ_  (C_*F_*F_)      // 1048576 = 2^20

// k-permutation within 8-groups (linear-GEMM k dims only):
// stored position of logical l:  pi(l) = 2*(l&3) + (l>>2)

// ---------------------------------------------------------------------------
// Scratch (device globals; no allocations allowed)
// ---------------------------------------------------------------------------
__device__ float g_lin[3][TOT_];     // q,k,v linear outputs [bc][f][w]
__device__ float g_conv[3][TOT_];    // V conv output uses slot 2
__device__ float g_xt[TOT_];         // x transposed [bc][w][f~pi], tf32-rounded
__device__ float g_qt[TOT_];         // Q conv+rot transposed [bch][w][d]
__device__ float g_kt[TOT_];         // K conv+rot transposed [bch][w][d]
__device__ float g_atT[TOT_];        // attention out [bc][w][f~pi], tf32-rounded
__device__ float g_wr[4][WSZ_];      // tf32-rounded weights, f_in dim pi-permuted
__device__ float2 g_rottab[32 * 1024];

// ---------------------------------------------------------------------------
// helpers
// ---------------------------------------------------------------------------
__device__ __forceinline__ unsigned tf32r(float x) {
    unsigned u;
    asm("cvt.rna.tf32.f32 %0, %1;" : "=r"(u) : "f"(x));
    return u;
}
__device__ __forceinline__ float tf32f(float x) { return __uint_as_float(tf32r(x)); }
__device__ __forceinline__ unsigned smem_u32(const void* p) {
    unsigned a;
    asm("{ .reg .u64 t; cvta.to.shared.u64 t, %1; cvt.u32.u64 %0, t; }" : "=r"(a) : "l"(p));
    return a;
}
__device__ __forceinline__ void cp16(unsigned dst, const void* src) {
    asm volatile("cp.async.cg.shared.global [%0], [%1], 16;" :: "r"(dst), "l"(src));
}
#define CP_COMMIT() asm volatile("cp.async.commit_group;")
#define CP_WAIT0()  asm volatile("cp.async.wait_group 0;")

#define MMA8(d, a, b) \
    asm volatile("mma.sync.aligned.m16n8k8.row.col.f32.tf32.tf32.f32 " \
        "{%0,%1,%2,%3}, {%4,%5,%6,%7}, {%8,%9}, {%0,%1,%2,%3};" \
        : "+f"((d)[0]), "+f"((d)[1]), "+f"((d)[2]), "+f"((d)[3]) \
        : "r"((a)[0]), "r"((a)[1]), "r"((a)[2]), "r"((a)[3]), \
          "r"((b)[0]), "r"((b)[1]))

// ---------------------------------------------------------------------------
// Rotary cos/sin table
// ---------------------------------------------------------------------------
__global__ void __launch_bounds__(256) rot_table_kernel()
{
    int id = blockIdx.x * 256 + threadIdx.x;
    if (id >= 32 * 1024) return;
    int j = id >> 10, w = id & (W_ - 1);
    float inv = (float)exp(-log(10000.0) * ((double)(2 * j) / 64.0));
    float ang = (float)w * inv;
    float sn, cs;
    sincosf(ang, &sn, &cs);
    g_rottab[id] = make_float2(cs, sn);
}

// ---------------------------------------------------------------------------
// Round 4 weight tensors to tf32 into g_wr, f_in dim stored pi-permuted.
// ---------------------------------------------------------------------------
__global__ void __launch_bounds__(256) round_w_kernel(
    const float* __restrict__ w0, const float* __restrict__ w1,
    const float* __restrict__ w2, const float* __restrict__ w3)
{
    int i = blockIdx.x * 256 + threadIdx.x;   // over 4*WSZ_
    int which = i >> 20;
    int off   = i & (WSZ_ - 1);
    int s = off & 7;
    int src_off = (off & ~7) | ((s & 1) * 4 + (s >> 1));   // inverse-pi
    const float* src = which == 0 ? w0 : which == 1 ? w1 : which == 2 ? w2 : w3;
    (&g_wr[0][0])[i] = tf32f(src[src_off]);
}

// ---------------------------------------------------------------------------
// Plane transpose x -> xt: [bc][F][W] -> [bc][W][F~pi], tf32-rounded
// ---------------------------------------------------------------------------
__global__ void transpose_kernel(const float* __restrict__ in,
                                 float* __restrict__ out, int R)
{
    __shared__ float t[32][33];
    const int p  = blockIdx.z;
    const int r0 = blockIdx.y * 32, w0 = blockIdx.x * 32;
    const int tx = threadIdx.x, ty = threadIdx.y;        // (32, 8)
    const float* ip = in  + (size_t)p * R * W_;
    float*       op = out + (size_t)p * R * W_;
    #pragma unroll
    for (int i = 0; i < 4; i++)
        t[ty + i*8][tx] = ip[(size_t)(r0 + ty + i*8) * W_ + w0 + tx];
    __syncthreads();
    const int f  = r0 + tx;
    const int fp = (f & ~7) | (2 * (f & 3) + ((f >> 2) & 1));   // pi
    #pragma unroll
    for (int i = 0; i < 4; i++)
        op[(size_t)(w0 + ty + i*8) * R + fp] = tf32f(t[tx][ty + i*8]);
}

// ---------------------------------------------------------------------------
// tf32 GEMM (cp.async 2-stage, pi-permuted k => LDS.64 fragment loads,
// hoisted fragment base pointers):
//   Y[which][bc][m][n] = sum_k A_which[c][m][k] * B[bc][n][k]
// CTA 128x128, BK=32, 8 warps (2x4), warp 64x32.  smem pitch 40 floats.
// ---------------------------------------------------------------------------
#define GEMM_SMEM (2 * 2 * 128 * 40 * 4)   // 81920 B -> 2 CTAs/SM

__global__ void __launch_bounds__(256, 2) gemm_tf32_kernel(
    const float* __restrict__ A0, const float* __restrict__ A1,
    const float* __restrict__ A2,
    const float* __restrict__ Bm,   // [BC][1024][512~pi]
    float* __restrict__ Y)          // [which][BC][512][1024]
{
    extern __shared__ float gsm[];
    const int tid = threadIdx.x;
    const int wid = tid >> 5, lane = tid & 31;
    const int g = lane >> 2, t4 = lane & 3;
    const int z = blockIdx.z, which = z >> 3, bc = z & 7, c = bc & (C_ - 1);
    const int m0 = blockIdx.y * 128, n0 = blockIdx.x * 128;
    const int wm0 = (wid >> 2) * 64, wn0 = (wid & 3) * 32;

    const float* Aw = which == 0 ? A0 : which == 1 ? A1 : A2;
    const float* Ab = Aw + ((size_t)c  * F_ + m0) * F_;
    const float* Bb = Bm + ((size_t)bc * W_ + n0) * F_;
    const unsigned s0 = smem_u32(gsm);

    const int aoff = (wm0 + g) * 40 + 2 * t4;
    const int boff = 5120 + (wn0 + g) * 40 + 2 * t4;

    #define ISSUE(kt, b) do {                                                  \
        unsigned aB = s0 + (b) * 40960;                                        \
        unsigned bB = aB + 20480;                                              \
        _Pragma("unroll")                                                      \
        for (int t = 0; t < 4; t++) {                                          \
            int ch = tid + t * 256;                                            \
            int row = ch >> 3, c4 = (ch & 7) * 4;                              \
            cp16(aB + (unsigned)(row * 40 + c4) * 4,                           \
                 Ab + (size_t)row * F_ + (kt) * 32 + c4);                      \
            cp16(bB + (unsigned)(row * 40 + c4) * 4,                           \
                 Bb + (size_t)row * F_ + (kt) * 32 + c4);                      \
        }                                                                      \
        CP_COMMIT();                                                           \
    } while (0)

    float acc[4][4][4] = {};
    ISSUE(0, 0);

    for (int kt = 0; kt < 16; kt++) {
        const int buf = kt & 1;
        CP_WAIT0();
        __syncthreads();
        if (kt + 1 < 16) ISSUE(kt + 1, buf ^ 1);

        const float* aw = gsm + buf * 10240 + aoff;
        const float* bw = gsm + buf * 10240 + boff;
        #pragma unroll
        for (int k8 = 0; k8 < 4; k8++) {
            const int kk = k8 * 8;
            unsigned a[4][4], b[4][2];
            #pragma unroll
            for (int mf = 0; mf < 4; mf++) {
                float2 p = *(const float2*)(aw + mf*640 + kk);
                float2 q = *(const float2*)(aw + mf*640 + 320 + kk);
                a[mf][0] = __float_as_uint(p.x);
                a[mf][1] = __float_as_uint(q.x);
                a[mf][2] = __float_as_uint(p.y);
                a[mf][3] = __float_as_uint(q.y);
            }
            #pragma unroll
            for (int nf = 0; nf < 4; nf++) {
                float2 p = *(const float2*)(bw + nf*320 + kk);
                b[nf][0] = __float_as_uint(p.x);
                b[nf][1] = __float_as_uint(p.y);
            }
            #pragma unroll
            for (int mf = 0; mf < 4; mf++)
                #pragma unroll
                for (int nf = 0; nf < 4; nf++)
                    MMA8(acc[mf][nf], a[mf], b[nf]);
        }
    }
    #undef ISSUE

    float* Yb = Y + (size_t)which * TOT_ + (size_t)bc * PLANE_;
    #pragma unroll
    for (int mf = 0; mf < 4; mf++) {
        #pragma unroll
        for (int nf = 0; nf < 4; nf++) {
            int m = m0 + wm0 + mf*16 + g;
            int n = n0 + wn0 + nf*8 + 2*t4;
            float* y0 = Yb + (size_t)m * W_ + n;
            *(float2*)y0          = make_float2(acc[mf][nf][0], acc[mf][nf][1]);
            *(float2*)(y0 + 8*W_) = make_float2(acc[mf][nf][2], acc[mf][nf][3]);
        }
    }
}

// ---------------------------------------------------------------------------
// FUSED conv + bias + rotary + transpose for Q AND K (merged launch):
//   sel = blockIdx.z >> 3 chooses (Xq,wq,bq -> Tq) vs (Xk,wk,bk -> Tk)
// ---------------------------------------------------------------------------
__global__ void __launch_bounds__(256) convrot_t_kernel(
    const float* __restrict__ Xq, const float* __restrict__ Wcq,
    const float* __restrict__ bq, float* __restrict__ Tq,
    const float* __restrict__ Xk, const float* __restrict__ Wck,
    const float* __restrict__ bk, float* __restrict__ Tk)
{
    __shared__ float ws[C_*C_*KW];
    __shared__ float bs[C_];
    __shared__ float t[128][65];

    const int sel = blockIdx.z >> 3;
    const int bc  = blockIdx.z & 7;
    const float* X    = sel ? Xk  : Xq;
    const float* Wc   = sel ? Wck : Wcq;
    const float* bias = sel ? bk  : bq;
    float*       T    = sel ? Tk  : Tq;

    const int tid = threadIdx.x;
    if (tid < C_*C_*KW) ws[tid] = Wc[tid];
    if (tid < C_)       bs[tid] = bias[tid];
    __syncthreads();

    const int w0 = blockIdx.x * 128;
    const int h  = blockIdx.y;
    const int b  = bc >> 2, o = bc & (C_ - 1);

    #pragma unroll
    for (int tk = 0; tk < 16; tk++) {
        int id = tid + tk * 256;          // 0..4095
        int wl = id & 127;
        int j  = id >> 7;                 // 0..31
        int w  = w0 + wl;
        int f0 = h * DH_ + 2 * j;

        float s0 = bs[o], s1 = bs[o];
        #pragma unroll
        for (int i = 0; i < C_; i++) {
            const float* x0 = X + ((size_t)(b*C_ + i) * F_ + f0) * W_ + w;
            const float* x1 = x0 + W_;
            const float* wr = ws + (o*C_ + i) * KW;
            if (w > 0)      { s0 += wr[0] * x0[-1]; s1 += wr[0] * x1[-1]; }
                              s0 += wr[1] * x0[0];  s1 += wr[1] * x1[0];
            if (w < W_ - 1) { s0 += wr[2] * x0[1];  s1 += wr[2] * x1[1]; }
        }
        float2 cssn = g_rottab[j * W_ + w];
        t[wl][2*j]     = tf32f(s0 * cssn.x - s1 * cssn.y);
        t[wl][2*j + 1] = tf32f(s1 * cssn.x + s0 * cssn.y);
    }
    __syncthreads();

    const int bch = bc * H_ + h;
    float* Tb = T + ((size_t)bch * W_ + w0) * DH_;
    const int row = tid >> 4;           // 0..15
    const int d4  = (tid & 15) * 4;
    #pragma unroll
    for (int p = 0; p < 8; p++) {
        int wl = row + p * 16;
        float4 v = make_float4(t[wl][d4], t[wl][d4+1], t[wl][d4+2], t[wl][d4+3]);
        *(float4*)(Tb + (size_t)wl * DH_ + d4) = v;
    }
}

// ---------------------------------------------------------------------------
// Conv2d + bias for V (tf32-rounded output, layout unchanged [bc][f][w])
// ---------------------------------------------------------------------------
__global__ void __launch_bounds__(256) conv_v_kernel(
    const float* __restrict__ X, const float* __restrict__ Wc,
    const float* __restrict__ bias, float* __restrict__ Y)
{
    __shared__ float ws[C_*C_*KW];
    __shared__ float bs[C_];
    if (threadIdx.x < C_*C_*KW) ws[threadIdx.x] = Wc[threadIdx.x];
    if (threadIdx.x < C_)       bs[threadIdx.x] = bias[threadIdx.x];
    __syncthreads();

    int idx = blockIdx.x * 256 + threadIdx.x;     // over TOT_/2
    if (idx >= TOT_/2) return;
    int w  = idx & (W_ - 1);
    int fp = (idx >> 10) & 255;
    int o  = (idx >> 18) & (C_ - 1);
    int b  = idx >> 20;
    int f0 = fp * 2;

    float s0 = bs[o], s1 = bs[o];
    #pragma unroll
    for (int i = 0; i < C_; i++) {
        const float* x0 = X + ((size_t)(b*C_ + i) * F_ + f0) * W_ + w;
        const float* x1 = x0 + W_;
        const float* wr = ws + (o*C_ + i) * KW;
        if (w > 0)       { s0 += wr[0] * x0[-1]; s1 += wr[0] * x1[-1]; }
                           s0 += wr[1] * x0[0];  s1 += wr[1] * x1[0];
        if (w < W_ - 1)  { s0 += wr[2] * x0[1];  s1 += wr[2] * x1[1]; }
    }

    size_t obase = ((size_t)(b*C_ + o) * F_ + f0) * W_ + w;
    Y[obase]      = tf32f(s0);
    Y[obase + W_] = tf32f(s1);
}

// ---------------------------------------------------------------------------
// qk = scale*Qt.Kt^T + prev + mask  (tf32 mma, pre-rounded Qt/Kt).
// Per (bch): M=N=1024, K=64.  CTA 128x128, one-shot smem, 8 warps (2x4).
// ---------------------------------------------------------------------------
#define QK_SMEM (2 * 128 * 68 * 4)

__global__ void __launch_bounds__(256, 2) qk_mma_kernel(
    const float* __restrict__ Qt, const float* __restrict__ Kt,
    const float* __restrict__ prev, const float* __restrict__ mask,
    float* __restrict__ qk)
{
    extern __shared__ unsigned qsm[];
    unsigned (*Qs)[68] = (unsigned (*)[68])qsm;
    unsigned (*Ks)[68] = (unsigned (*)[68])(qsm + 128 * 68);

    const int tid = threadIdx.x;
    const int wid = tid >> 5, lane = tid & 31;
    const int g = lane >> 2, t4 = lane & 3;
    const int bch = blockIdx.z;
    const int q0 = blockIdx.y * 128, k0 = blockIdx.x * 128;
    const int wm0 = (wid >> 2) * 64, wn0 = (wid & 3) * 32;

    const float* Qb = Qt + ((size_t)bch * W_ + q0) * DH_;
    const float* Kb = Kt + ((size_t)bch * W_ + k0) * DH_;

    #pragma unroll
    for (int t = 0; t < 8; t++) {
        int idx = tid + t * 256;          // 0..2047
        int row = idx >> 4;
        int c4  = (idx & 15) * 4;
        *(uint4*)&Qs[row][c4] = *(const uint4*)(Qb + (size_t)row * DH_ + c4);
        *(uint4*)&Ks[row][c4] = *(const uint4*)(Kb + (size_t)row * DH_ + c4);
    }
    __syncthreads();

    float acc[4][4][4] = {};
    #pragma unroll
    for (int k8 = 0; k8 < 8; k8++) {
        const int kk = k8 * 8;
        unsigned a[4][4], b[4][2];
        #pragma unroll
        for (int mf = 0; mf < 4; mf++) {
            int r = wm0 + mf*16 + g;
            a[mf][0] = Qs[r][kk + t4];
            a[mf][1] = Qs[r + 8][kk + t4];
            a[mf][2] = Qs[r][kk + t4 + 4];
            a[mf][3] = Qs[r + 8][kk + t4 + 4];
        }
        #pragma unroll
        for (int nf = 0; nf < 4; nf++) {
            int r = wn0 + nf*8 + g;
            b[nf][0] = Ks[r][kk + t4];
            b[nf][1] = Ks[r][kk + t4 + 4];
        }
        #pragma unroll
        for (int mf = 0; mf < 4; mf++)
            #pragma unroll
            for (int nf = 0; nf < 4; nf++)
                MMA8(acc[mf][nf], a[mf], b[nf]);
    }

    const float scale = 0.044194173824159216f;   // 1/sqrt(512)
    #pragma unroll
    for (int mf = 0; mf < 4; mf++) {
        #pragma unroll
        for (int nf = 0; nf < 4; nf++) {
            int q  = q0 + wm0 + mf*16 + g;
            int kp = k0 + wn0 + nf*8 + 2*t4;
            #pragma unroll
            for (int rr = 0; rr < 2; rr++) {
                int qq = q + rr * 8;
                size_t o = ((size_t)bch * W_ + qq) * W_ + kp;
                float2 pv = *(const float2*)(prev + o);
                float2 mv = *(const float2*)(mask + (size_t)qq * W_ + kp);
                float2 r;
                r.x = acc[mf][nf][2*rr+0] * scale + pv.x + mv.x;
                r.y = acc[mf][nf][2*rr+1] * scale + pv.y + mv.y;
                *(float2*)(qk + o) = r;
            }
        }
    }
}

// ---------------------------------------------------------------------------
// AV with fused row-sum.  CTA order REVERSED vs qk's write order so the
// qk re-read consumes the most-recently-written slabs first (L2-resident):
//   bch = 63 - blockIdx.y, q-tile = 7 - blockIdx.x.
//   AT[bc][q][pi(h*64+d)] = (1/S_q) * sum_k exp(qk) * V
// ---------------------------------------------------------------------------
#define AV_SMEM ((128*68 + 64*68 + 128*16 + 128) * 4)

__global__ void __launch_bounds__(256, 2) av_mma_kernel(
    const float* __restrict__ qk, const float* __restrict__ V,
    float* __restrict__ AT)
{
    extern __shared__ unsigned asm_[];
    unsigned (*Ps)[68] = (unsigned (*)[68])asm_;
    unsigned (*Vs)[68] = (unsigned (*)[68])(asm_ + 128 * 68);
    float* ssum = (float*)(asm_ + 128*68 + 64*68);   // [128][16]
    float* srs  = ssum + 128*16;                     // [128]

    const int tid = threadIdx.x;
    const int wid = tid >> 5, lane = tid & 31;
    const int g = lane >> 2, t4 = lane & 3;
    const int bch = (BCH_ - 1) - blockIdx.y;          // reversed
    const int q0  = ((W_/128 - 1) - blockIdx.x) * 128; // reversed
    const int h   = bch & (H_ - 1);
    const int bc  = bch >> 3;
    const int wm0 = (wid >> 1) * 32, wn0 = (wid & 1) * 32;

    const float* qrow = qk + ((size_t)bch * W_ + q0) * W_;
    const float* Vb   = V + ((size_t)bc * F_ + h * DH_) * W_;

    // zero row-sum slots
    #pragma unroll
    for (int t = 0; t < 8; t++) ssum[tid + t * 256] = 0.f;

    float acc[2][4][4] = {};
    for (int kt = 0; kt < 16; kt++) {
        const int k0 = kt * 64;
        __syncthreads();
        #pragma unroll
        for (int t = 0; t < 8; t++) {
            int idx = tid + t * 256;          // 0..2047
            int row = idx >> 4;
            int c16 = idx & 15;
            int c4  = c16 * 4;
            float4 x = *(const float4*)(qrow + (size_t)row * W_ + k0 + c4);
            float e0 = __expf(x.x), e1 = __expf(x.y);
            float e2 = __expf(x.z), e3 = __expf(x.w);
            ssum[row * 16 + c16] += (e0 + e1) + (e2 + e3);
            *(uint4*)&Ps[row][c4] = make_uint4(tf32r(e0), tf32r(e1), tf32r(e2), tf32r(e3));
        }
        #pragma unroll
        for (int t = 0; t < 4; t++) {
            int idx = tid + t * 256;          // 0..1023
            int row = idx >> 4;
            int c4  = (idx & 15) * 4;
            *(uint4*)&Vs[row][c4] = *(const uint4*)(Vb + (size_t)row * W_ + k0 + c4);
        }
        __syncthreads();
        #pragma unroll
        for (int k8 = 0; k8 < 8; k8++) {
            const int kk = k8 * 8;
            unsigned a[2][4], b[4][2];
            #pragma unroll
            for (int mf = 0; mf < 2; mf++) {
                int r = wm0 + mf*16 + g;
                a[mf][0] = Ps[r][kk + t4];
                a[mf][1] = Ps[r + 8][kk + t4];
                a[mf][2] = Ps[r][kk + t4 + 4];
                a[mf][3] = Ps[r + 8][kk + t4 + 4];
            }
            #pragma unroll
            for (int nf = 0; nf < 4; nf++) {
                int r = wn0 + nf*8 + g;
                b[nf][0] = Vs[r][kk + t4];
                b[nf][1] = Vs[r][kk + t4 + 4];
            }
            #pragma unroll
            for (int mf = 0; mf < 2; mf++)
                #pragma unroll
                for (int nf = 0; nf < 4; nf++)
                    MMA8(acc[mf][nf], a[mf], b[nf]);
        }
    }

    // final row-sum reduction (fixed order => deterministic)
    __syncthreads();
    if (tid < 128) {
        float s = 0.f;
        #pragma unroll
        for (int j = 0; j < 16; j++) s += ssum[tid * 16 + j];
        srs[tid] = 1.0f / s;
    }
    __syncthreads();

    // pi positions for the pair (2*t4, 2*t4+1) within the 8-group
    const int l0 = 2 * t4,     s0p = 2 * (l0 & 3) + (l0 >> 2);
    const int l1 = 2 * t4 + 1, s1p = 2 * (l1 & 3) + (l1 >> 2);

    #pragma unroll
    for (int mf = 0; mf < 2; mf++) {
        #pragma unroll
        for (int nf = 0; nf < 4; nf++) {
            int ql = wm0 + mf*16 + g;
            int dg = wn0 + nf*8;                 // 8-group base of d
            #pragma unroll
            for (int rr = 0; rr < 2; rr++) {
                int q = ql + rr * 8;
                float sc = srs[q];
                size_t ob = ((size_t)bc * W_ + q0 + q) * F_ + h * DH_ + dg;
                AT[ob + s0p] = tf32f(acc[mf][nf][2*rr+0] * sc);
                AT[ob + s1p] = tf32f(acc[mf][nf][2*rr+1] * sc);
            }
        }
    }
}

// ---------------------------------------------------------------------------
extern "C" void kernel_launch(void* const* d_in, const int* in_sizes, int n_in,
                              void* d_out, int out_size)
{
    const float* x    = (const float*)d_in[0];
    const float* prev = (const float*)d_in[1];
    const float* mask = (const float*)d_in[2];
    const float* wq   = (const float*)d_in[3];
    const float* wqc  = (const float*)d_in[4];
    const float* bq   = (const float*)d_in[5];
    const float* wk   = (const float*)d_in[6];
    const float* wkc  = (const float*)d_in[7];
    const float* bk   = (const float*)d_in[8];
    const float* wv   = (const float*)d_in[9];
    const float* wvc  = (const float*)d_in[10];
    const float* bv   = (const float*)d_in[11];
    const float* wo   = (const float*)d_in[12];

    float* out = (float*)d_out;            // [B,C,F,W]
    float* qk  = out + (size_t)TOT_;       // [B,C,H,W,W]

    float *lin_base, *conv_base, *xt, *qt, *kt, *atT, *wr;
    cudaGetSymbolAddress((void**)&lin_base,  g_lin);
    cudaGetSymbolAddress((void**)&conv_base, g_conv);
    cudaGetSymbolAddress((void**)&xt,  g_xt);
    cudaGetSymbolAddress((void**)&qt,  g_qt);
    cudaGetSymbolAddress((void**)&kt,  g_kt);
    cudaGetSymbolAddress((void**)&atT, g_atT);
    cudaGetSymbolAddress((void**)&wr,  g_wr);

    float* lin0  = lin_base;
    float* cbuf2 = conv_base + (size_t)2*TOT_;

    rot_table_kernel<<<128, 256>>>();
    round_w_kernel<<<(4*WSZ_)/256, 256>>>(wq, wk, wv, wo);

    // x [bc][f][w] -> xt [bc][w][f~pi] (rounded)
    transpose_kernel<<<dim3(32, 16, BC_), dim3(32, 8)>>>(x, xt, F_);

    cudaFuncSetAttribute(gemm_tf32_kernel,
                         cudaFuncAttributeMaxDynamicSharedMemorySize, GEMM_SMEM);
    // combined QKV: grid.z = 3*8
    gemm_tf32_kernel<<<dim3(W_/128, F_/128, 24), 256, GEMM_SMEM>>>(
        wr + 0*WSZ_, wr + 1*WSZ_, wr + 2*WSZ_, xt, lin0);

    // merged conv+rotary+transpose for Q and K (one launch, z = 16)
    convrot_t_kernel<<<dim3(W_/128, H_, 16), 256>>>(
        lin0 + 0*(size_t)TOT_, wqc, bq, qt,
        lin0 + 1*(size_t)TOT_, wkc, bk, kt);
    // V conv (layout unchanged)
    conv_v_kernel<<<(TOT_/2)/256, 256>>>(lin0 + 2*(size_t)TOT_, wvc, bv, cbuf2);

    cudaFuncSetAttribute(qk_mma_kernel,
                         cudaFuncAttributeMaxDynamicSharedMemorySize, QK_SMEM);
    qk_mma_kernel<<<dim3(8, 8, BCH_), 256, QK_SMEM>>>(qt, kt, prev, mask, qk);

    cudaFuncSetAttribute(av_mma_kernel,
                         cudaFuncAttributeMaxDynamicSharedMemorySize, AV_SMEM);
    av_mma_kernel<<<dim3(W_/128, BCH_), 256, AV_SMEM>>>(qk, cbuf2, atT);

    // O gemm: which = 0 only
    gemm_tf32_kernel<<<dim3(W_/128, F_/128, 8), 256, GEMM_SMEM>>>(
        wr + 3*WSZ_, wr + 3*WSZ_, wr + 3*WSZ_, atT, out);
}